// round 12
// baseline (speedup 1.0000x reference)
#include <cuda_runtime.h>
#include <cuda_fp16.h>
#include <cstdint>

#define DDIM 64
#define KCODES 1024
#define NTOK 131072
#define TM 128
#define NTHREADS 512
#define PASSES 4
#define CPASS 256
#define CAP 8
#define MARGIN 0.15f

// ---------------- smem layout (bytes) ----------------
#define OFF_XF    0        // f32 [128][65]  = 33280 (exact, for xn + rescore)
#define OFF_XH    33280    // u32 [64][128]  = 32768 (half2 {x,x} replicated)
#define OFF_CS    66048    // u32 [64][128]  = 32768 (half2 code pairs, per pass)
#define OFF_CN    98816    // f32 [1024]     = 4096
#define OFF_CAND  102912   // u16 [16][128][8] = 32768
#define OFF_REDV  135680   // f32 [16][128]  = 8192
#define OFF_GB    143872   // f32 [128]      = 512
#define OFF_RV2   144384   // f32 [4][128]   = 2048
#define OFF_RI2   146432   // int [4][128]   = 2048
#define OFF_XNS   148480   // f32 [128]
#define OFF_WIX   148992   // int [128]
#define OFF_SCNT  149504   // u8  [16][128]  = 2048 (255 = overflow)
#define SMEM_BYTES 151552

__device__ float g_cn[KCODES];                    // ||c||^2, sequential order (bit-matches ref)
__device__ __align__(16) uint32_t g_ch[DDIM * (KCODES / 2)];  // half2 {c_2j,c_2j+1} [d][j]

__global__ void vq_prep(const float* __restrict__ cb) {
    int k = blockIdx.x * blockDim.x + threadIdx.x;
    if (k >= KCODES) return;
    const float* cr = cb + k * DDIM;
    float acc = 0.f;
#pragma unroll
    for (int d = 0; d < DDIM; d++) acc = __fadd_rn(acc, __fmul_rn(cr[d], cr[d]));
    g_cn[k] = acc;
    if (k < KCODES / 2) {
        const float* c0 = cb + (2 * k) * DDIM;
        const float* c1 = cb + (2 * k + 1) * DDIM;
#pragma unroll
        for (int d = 0; d < DDIM; d++) {
            __half2 p = __floats2half2_rn(c0[d], c1[d]);
            g_ch[d * (KCODES / 2) + k] = *(uint32_t*)&p;
        }
    }
}

__device__ __forceinline__ uint32_t smem_u32(const void* p) {
    uint32_t a;
    asm("{ .reg .u64 t; cvta.to.shared.u64 t, %1; cvt.u32.u64 %0, t; }" : "=r"(a) : "l"(p));
    return a;
}
__device__ __forceinline__ uint4 lds128(uint32_t a) {
    uint4 v;
    asm volatile("ld.shared.v4.u32 {%0,%1,%2,%3}, [%4];"
                 : "=r"(v.x), "=r"(v.y), "=r"(v.z), "=r"(v.w) : "r"(a));
    return v;
}

// forced-register HFMA2: acc, x, c are plain uint32 registers
#define HFMA2(acc, x, c) asm("fma.rn.f16x2 %0, %1, %2, %0;" : "+r"(acc) : "r"(x), "r"(c))

// exact rescore: bit-matches reference (verified R2/R4-R11)
__device__ __forceinline__ float exact_d2(const float* __restrict__ cb,
                                          const float* __restrict__ xrow,
                                          float xn, float cnk, int k) {
    const float4* cr = (const float4*)(cb + k * DDIM);
    float s = 0.f;
#pragma unroll 4
    for (int i = 0; i < 16; i++) {
        float4 v = cr[i];
        s = __fmaf_rn(xrow[4 * i + 0], v.x, s);
        s = __fmaf_rn(xrow[4 * i + 1], v.y, s);
        s = __fmaf_rn(xrow[4 * i + 2], v.z, s);
        s = __fmaf_rn(xrow[4 * i + 3], v.w, s);
    }
    return __fadd_rn(__fsub_rn(xn, __fmul_rn(2.0f, s)), cnk);
}

__device__ __forceinline__ void lex_scan_slice(const float* cb, const float* Cn,
                                               const float* xrow, float xn, int w,
                                               float& bv, int& bi) {
#pragma unroll 1
    for (int p = 0; p < PASSES; p++)
#pragma unroll 1
        for (int j = 0; j < 16; j++) {
            int k = p * CPASS + w * 16 + j;
            float d2 = exact_d2(cb, xrow, xn, Cn[k], k);
            if (d2 < bv || (d2 == bv && k < bi)) { bv = d2; bi = k; }
        }
}

__global__ __launch_bounds__(NTHREADS, 1)
void vq_main(const float* __restrict__ h, const float* __restrict__ cb,
             float* __restrict__ outZ, float* __restrict__ outQ) {
    extern __shared__ char smem[];
    float*    Xf   = (float*)(smem + OFF_XF);
    uint32_t* Xh   = (uint32_t*)(smem + OFF_XH);
    uint32_t* Cs   = (uint32_t*)(smem + OFF_CS);
    float*    Cn   = (float*)(smem + OFF_CN);
    uint16_t* cand = (uint16_t*)(smem + OFF_CAND);
    float*    redv = (float*)(smem + OFF_REDV);
    float*    gb   = (float*)(smem + OFF_GB);
    float*    rv2  = (float*)(smem + OFF_RV2);
    int*      ri2  = (int*)(smem + OFF_RI2);
    float*    xns  = (float*)(smem + OFF_XNS);
    int*      wix  = (int*)(smem + OFF_WIX);
    uint8_t*  sCnt = (uint8_t*)(smem + OFF_SCNT);
    const uint32_t sbase = smem_u32(smem);

    const int tid = threadIdx.x;
    const int w = tid >> 5;
    const int l = tid & 31;
    const int n0 = blockIdx.x * TM;
    const int bb_ = n0 >> 12;
    const long base = (long)bb_ * 262144 + (n0 & 4095);

    // ---- Xf [t][65]: coalesced d-major gmem reads ----
    for (int i = tid; i < 64 * 32; i += NTHREADS) {
        int d = i >> 5, t4 = i & 31;
        float4 v = *(const float4*)(h + base + (long)d * 4096 + t4 * 4);
        Xf[(t4 * 4 + 0) * 65 + d] = v.x;
        Xf[(t4 * 4 + 1) * 65 + d] = v.y;
        Xf[(t4 * 4 + 2) * 65 + d] = v.z;
        Xf[(t4 * 4 + 3) * 65 + d] = v.w;
    }
    for (int i = tid; i < KCODES; i += NTHREADS) Cn[i] = g_cn[i];
    for (int i = tid; i < 64 * 128 / 4; i += NTHREADS)
        *(uint4*)&Cs[i * 4] = *(const uint4*)&g_ch[(i >> 5) * 512 + ((i & 31) << 2)];
    __syncthreads();

    // ---- exact xn (sequential mul-then-add; reference order) ----
    if (tid < 128) {
        float acc = 0.f;
#pragma unroll
        for (int d = 0; d < 64; d++) {
            float xv = Xf[tid * 65 + d];
            acc = __fadd_rn(acc, __fmul_rn(xv, xv));
        }
        xns[tid] = acc;
    }
    // Xh: replicated half2 {x,x}, [d][t]
    for (int i = tid; i < 64 * 128; i += NTHREADS) {
        int d = i >> 7, t = i & 127;
        __half hx = __float2half_rn(Xf[t * 65 + d]);
        __half2 p = __halves2half2(hx, hx);
        Xh[d * 128 + t] = *(uint32_t*)&p;
    }
    __syncthreads();

    float xnr[4];
    {
        float4 v = *(const float4*)&xns[4 * l];
        xnr[0] = v.x; xnr[1] = v.y; xnr[2] = v.z; xnr[3] = v.w;
    }
    float best[4] = {3.4e38f, 3.4e38f, 3.4e38f, 3.4e38f};
    int cnt[4] = {0, 0, 0, 0};

    const uint32_t xaddr = sbase + OFF_XH + 16u * l;   // this thread's 4 tokens
    const uint32_t caddr = sbase + OFF_CS + 32u * w;   // this warp's 8 code pairs

#pragma unroll 1
    for (int p = 0; p < PASSES; p++) {
        // 32 named accumulator registers: A{j}{t}, j = code pair 0..7, t = token 0..3
        uint32_t A00=0,A01=0,A02=0,A03=0, A10=0,A11=0,A12=0,A13=0,
                 A20=0,A21=0,A22=0,A23=0, A30=0,A31=0,A32=0,A33=0,
                 A40=0,A41=0,A42=0,A43=0, A50=0,A51=0,A52=0,A53=0,
                 A60=0,A61=0,A62=0,A63=0, A70=0,A71=0,A72=0,A73=0;

#pragma unroll 2
        for (int d = 0; d < 64; d++) {
            uint4 xv = lds128(xaddr + (uint32_t)(d * 512));
            uint32_t ca = caddr + (uint32_t)(d * 512);
            uint4 c0 = lds128(ca);        // pairs j=0..3 (warp-uniform broadcast)
            uint4 c1 = lds128(ca + 16);   // pairs j=4..7
            HFMA2(A00, xv.x, c0.x); HFMA2(A01, xv.y, c0.x); HFMA2(A02, xv.z, c0.x); HFMA2(A03, xv.w, c0.x);
            HFMA2(A10, xv.x, c0.y); HFMA2(A11, xv.y, c0.y); HFMA2(A12, xv.z, c0.y); HFMA2(A13, xv.w, c0.y);
            HFMA2(A20, xv.x, c0.z); HFMA2(A21, xv.y, c0.z); HFMA2(A22, xv.z, c0.z); HFMA2(A23, xv.w, c0.z);
            HFMA2(A30, xv.x, c0.w); HFMA2(A31, xv.y, c0.w); HFMA2(A32, xv.z, c0.w); HFMA2(A33, xv.w, c0.w);
            HFMA2(A40, xv.x, c1.x); HFMA2(A41, xv.y, c1.x); HFMA2(A42, xv.z, c1.x); HFMA2(A43, xv.w, c1.x);
            HFMA2(A50, xv.x, c1.y); HFMA2(A51, xv.y, c1.y); HFMA2(A52, xv.z, c1.y); HFMA2(A53, xv.w, c1.y);
            HFMA2(A60, xv.x, c1.z); HFMA2(A61, xv.y, c1.z); HFMA2(A62, xv.z, c1.z); HFMA2(A63, xv.w, c1.z);
            HFMA2(A70, xv.x, c1.w); HFMA2(A71, xv.y, c1.w); HFMA2(A72, xv.z, c1.w); HFMA2(A73, xv.w, c1.w);
        }

        // epilogue: approx d2 from fp16 s, candidate collection
        const int kw = p * CPASS + w * 16;
#define EPI1(ACC, JJ, TT) { \
            __half2 hh = *(__half2*)&(ACC); \
            float2 s2 = __half22float2(hh); \
            int k0 = kw + 2 * (JJ); \
            float d2a = xnr[TT] - 2.0f * s2.x + Cn[k0]; \
            float d2b = xnr[TT] - 2.0f * s2.y + Cn[k0 + 1]; \
            if (fminf(d2a, d2b) < best[TT] + MARGIN) { \
                int slot = (w * 128 + 4 * l + (TT)) * CAP; \
                if (d2a < best[TT] + MARGIN) { \
                    if (cnt[TT] < CAP) cand[slot + cnt[TT]] = (uint16_t)k0; \
                    cnt[TT]++; \
                } \
                if (d2b < best[TT] + MARGIN) { \
                    if (cnt[TT] < CAP) cand[slot + cnt[TT]] = (uint16_t)(k0 + 1); \
                    cnt[TT]++; \
                } \
                best[TT] = fminf(best[TT], fminf(d2a, d2b)); \
            } }
        EPI1(A00, 0, 0) EPI1(A01, 0, 1) EPI1(A02, 0, 2) EPI1(A03, 0, 3)
        EPI1(A10, 1, 0) EPI1(A11, 1, 1) EPI1(A12, 1, 2) EPI1(A13, 1, 3)
        EPI1(A20, 2, 0) EPI1(A21, 2, 1) EPI1(A22, 2, 2) EPI1(A23, 2, 3)
        EPI1(A30, 3, 0) EPI1(A31, 3, 1) EPI1(A32, 3, 2) EPI1(A33, 3, 3)
        EPI1(A40, 4, 0) EPI1(A41, 4, 1) EPI1(A42, 4, 2) EPI1(A43, 4, 3)
        EPI1(A50, 5, 0) EPI1(A51, 5, 1) EPI1(A52, 5, 2) EPI1(A53, 5, 3)
        EPI1(A60, 6, 0) EPI1(A61, 6, 1) EPI1(A62, 6, 2) EPI1(A63, 6, 3)
        EPI1(A70, 7, 0) EPI1(A71, 7, 1) EPI1(A72, 7, 2) EPI1(A73, 7, 3)
#undef EPI1

        // share best across warps; reload Cs for next pass
        *(float4*)&redv[w * 128 + 4 * l] = make_float4(best[0], best[1], best[2], best[3]);
        __syncthreads();
        if (tid < 128) {
            float m = redv[tid];
#pragma unroll
            for (int ww = 1; ww < 16; ww++) m = fminf(m, redv[ww * 128 + tid]);
            gb[tid] = m;
        }
        if (p + 1 < PASSES) {
            for (int i = tid; i < 64 * 128 / 4; i += NTHREADS)
                *(uint4*)&Cs[i * 4] =
                    *(const uint4*)&g_ch[(i >> 5) * 512 + (p + 1) * 128 + ((i & 31) << 2)];
        }
        __syncthreads();
        {
            float4 gv = *(const float4*)&gb[4 * l];
            best[0] = fminf(best[0], gv.x); best[1] = fminf(best[1], gv.y);
            best[2] = fminf(best[2], gv.z); best[3] = fminf(best[3], gv.w);
        }
    }

#pragma unroll
    for (int t = 0; t < 4; t++)
        sCnt[w * 128 + 4 * l + t] = (uint8_t)(cnt[t] > CAP ? 255 : cnt[t]);
    __syncthreads();

    // ---- exact rescore: 4 threads per token, each covers 4 warps' lists (R10/R11-verified) ----
    {
        const int t = tid & 127;
        const int p4 = tid >> 7;
        const float* xrow = &Xf[t * 65];
        const float xn = xns[t];
        float bv = 3.4e38f;
        int bi = 0x7fffffff;
        for (int ww = p4 * 4; ww < p4 * 4 + 4; ww++) {
            int n = sCnt[ww * 128 + t];
            if (n == 255) {
                lex_scan_slice(cb, Cn, xrow, xn, ww, bv, bi);
            } else {
                for (int i = 0; i < n; i++) {
                    int k = cand[(ww * 128 + t) * CAP + i];
                    float d2 = exact_d2(cb, xrow, xn, Cn[k], k);
                    if (d2 < bv || (d2 == bv && k < bi)) { bv = d2; bi = k; }
                }
            }
        }
        rv2[p4 * 128 + t] = bv;
        ri2[p4 * 128 + t] = bi;
    }
    __syncthreads();

    if (tid < 128) {
        float bv = rv2[tid];
        int bi = ri2[tid];
#pragma unroll
        for (int p4 = 1; p4 < 4; p4++) {
            float v = rv2[p4 * 128 + tid];
            int i2 = ri2[p4 * 128 + tid];
            if (v < bv || (v == bv && i2 < bi)) { bv = v; bi = i2; }
        }
        wix[tid] = bi;
        if (outZ) outZ[n0 + tid] = (float)bi;
    }
    __syncthreads();

    // ---- q gather ----
    if (outQ) {
        for (int i = tid; i < 128 * 16; i += NTHREADS) {
            int tt = i >> 4, c4 = i & 15;
            float4 v = *(const float4*)&cb[wix[tt] * DDIM + c4 * 4];
            *(float4*)&outQ[(long)(n0 + tt) * DDIM + c4 * 4] = v;
        }
    }
}

extern "C" void kernel_launch(void* const* d_in, const int* in_sizes, int n_in,
                              void* d_out, int out_size) {
    const float* h = (const float*)d_in[0];
    const float* cb = (const float*)d_in[1];
    float* out = (float*)d_out;

    float* outZ = nullptr;
    float* outQ = nullptr;
    if (out_size >= NTOK + NTOK * DDIM) { outZ = out; outQ = out + NTOK; }
    else if (out_size == NTOK * DDIM)   { outQ = out; }
    else                                { outZ = out; }

    cudaFuncSetAttribute(vq_main, cudaFuncAttributeMaxDynamicSharedMemorySize, SMEM_BYTES);
    vq_prep<<<4, 256>>>(cb);
    vq_main<<<NTOK / TM, NTHREADS, SMEM_BYTES>>>(h, cb, outZ, outQ);
}

// round 13
// speedup vs baseline: 7.9654x; 7.9654x over previous
#include <cuda_runtime.h>
#include <cstdint>

#define DDIM 64
#define KCODES 1024
#define NTOK 131072
#define TM 128
#define NTHREADS 512
#define PASSES 4
#define CPASS 256

typedef unsigned long long ull;

// ---------------- smem layout (bytes) ----------------
#define OFF_XF   0                    // float [64][128] = 32768 (d-major)
#define OFF_CS   32768                // 2 x float [64][256] = 131072 (double-buffered)
#define CS_STRIDE 65536
#define OFF_CN   163840               // float [1024] = 4096
#define OFF_XNS  167936               // float [128]
#define OFF_WIX  168448               // int [128]
#define SMEM_BYTES 168960
// reduction overlays Cs after the last pass:
#define OFF_REDV OFF_CS               // float [16][128] = 8192
#define OFF_REDI (OFF_CS + 8192)      // int   [16][128] = 8192

__device__ float g_cn[KCODES];                        // ||c||^2 (sequential, ref order)
__device__ __align__(16) float g_cbT[DDIM * KCODES];  // transposed codebook [d][k]

__global__ void vq_prep(const float* __restrict__ cb) {
    int k = blockIdx.x * blockDim.x + threadIdx.x;
    if (k >= KCODES) return;
    float acc = 0.f;
#pragma unroll
    for (int d = 0; d < DDIM; d++) {
        float c = cb[k * DDIM + d];
        acc = __fadd_rn(acc, __fmul_rn(c, c));
        g_cbT[d * KCODES + k] = c;
    }
    g_cn[k] = acc;
}

__device__ __forceinline__ uint32_t smem_u32(const void* p) {
    uint32_t a;
    asm("{ .reg .u64 t; cvta.to.shared.u64 t, %1; cvt.u32.u64 %0, t; }" : "=r"(a) : "l"(p));
    return a;
}
__device__ __forceinline__ uint4 lds128(uint32_t a) {
    uint4 v;
    asm volatile("ld.shared.v4.u32 {%0,%1,%2,%3}, [%4];"
                 : "=r"(v.x), "=r"(v.y), "=r"(v.z), "=r"(v.w) : "r"(a));
    return v;
}
__device__ __forceinline__ void lds2u64(ull& a0, ull& a1, uint32_t a) {
    asm volatile("ld.shared.v2.b64 {%0,%1}, [%2];" : "=l"(a0), "=l"(a1) : "r"(a));
}
__device__ __forceinline__ ull rep2(uint32_t x) {
    ull r;
    asm("mov.b64 %0, {%1,%1};" : "=l"(r) : "r"(x));
    return r;
}
__device__ __forceinline__ void fma2(ull& acc, ull x, ull c) {
    asm("fma.rn.f32x2 %0, %1, %2, %0;" : "+l"(acc) : "l"(x), "l"(c));
}

// async-fill one pass's code tile: Cs[buf][d][256] <- g_cbT[d][p*256 + col]
__device__ __forceinline__ void issue_cs(uint32_t sbase, int buf, int p) {
#pragma unroll
    for (int k = 0; k < 8; k++) {
        int i = threadIdx.x + k * NTHREADS;          // uint4 slot 0..4095
        int d = i >> 6;
        int col = (i & 63) << 2;
        uint32_t dst = sbase + OFF_CS + buf * CS_STRIDE + (uint32_t)((d * 256 + col) * 4);
        const char* src = (const char*)(g_cbT + d * KCODES + p * CPASS + col);
        asm volatile("cp.async.ca.shared.global [%0], [%1], 16;"
                     :: "r"(dst), "l"(src) : "memory");
    }
    asm volatile("cp.async.commit_group;" ::: "memory");
}

__global__ __launch_bounds__(NTHREADS, 1)
void vq_main(const float* __restrict__ h, const float* __restrict__ cb,
             float* __restrict__ outZ, float* __restrict__ outQ) {
    extern __shared__ char smem[];
    float* Xf  = (float*)(smem + OFF_XF);    // [64][128]
    float* Cn  = (float*)(smem + OFF_CN);
    float* xns = (float*)(smem + OFF_XNS);
    int*   wix = (int*)(smem + OFF_WIX);
    float* redv = (float*)(smem + OFF_REDV);
    int*   redi = (int*)(smem + OFF_REDI);
    const uint32_t sbase = smem_u32(smem);

    const int tid = threadIdx.x;
    const int wid = tid >> 5;
    const int l = tid & 31;
    const int n0 = blockIdx.x * TM;
    const int b = n0 >> 12;
    const long base = (long)b * 262144 + (n0 & 4095);

    // kick off pass-0 code tile immediately (overlaps the Xf gmem loads below)
    issue_cs(sbase, 0, 0);

    // ---- Xf [d][t]: coalesced LDG.128 -> STS.128, conflict-free ----
    for (int i = tid; i < 64 * 32; i += NTHREADS) {
        int d = i >> 5, t4 = i & 31;
        *(float4*)&Xf[d * 128 + t4 * 4] =
            *(const float4*)(h + base + (long)d * 4096 + t4 * 4);
    }
    for (int i = tid; i < KCODES; i += NTHREADS) Cn[i] = g_cn[i];
    __syncthreads();

    // ---- exact xn (sequential mul-then-add; bit-matches reference, R2-verified) ----
    if (tid < 128) {
        float acc = 0.f;
#pragma unroll
        for (int d = 0; d < 64; d++) {
            float xv = Xf[d * 128 + tid];
            acc = __fadd_rn(acc, __fmul_rn(xv, xv));
        }
        xns[tid] = acc;
    }
    __syncthreads();

    float xnr[4];
    {
        float4 v = *(const float4*)&xns[4 * l];
        xnr[0] = v.x; xnr[1] = v.y; xnr[2] = v.z; xnr[3] = v.w;
    }
    float best[4] = {3.4e38f, 3.4e38f, 3.4e38f, 3.4e38f};
    int bidx[4] = {0, 0, 0, 0};

    const uint32_t xaddr = sbase + OFF_XF + 16u * l;  // this thread's 4 tokens

#pragma unroll 1
    for (int p = 0; p < PASSES; p++) {
        // buf[p&1] ready? (its group is the only pending one)
        asm volatile("cp.async.wait_group 0;" ::: "memory");
        __syncthreads();
        // prefetch pass p+1 into buf[(p+1)&1] (last read in pass p-1 -> barrier-safe)
        if (p + 1 < PASSES) issue_cs(sbase, (p + 1) & 1, p + 1);

        const uint32_t caddr = sbase + OFF_CS + (uint32_t)((p & 1) * CS_STRIDE) + 64u * wid;

        // acc[cp][t] = {s(k=2cp), s(k=2cp+1)} for token t (FFMA2 chain from 0 = R2-exact)
        ull acc[8][4];
#pragma unroll
        for (int cp = 0; cp < 8; cp++)
#pragma unroll
            for (int t = 0; t < 4; t++) acc[cp][t] = 0ull;

#pragma unroll 2
        for (int d = 0; d < 64; d++) {
            uint4 xv = lds128(xaddr + (uint32_t)(d * 512));
            ull x0 = rep2(xv.x), x1 = rep2(xv.y), x2 = rep2(xv.z), x3 = rep2(xv.w);
            uint32_t ca = caddr + (uint32_t)(d * 1024);
#pragma unroll
            for (int cq = 0; cq < 4; cq++) {
                ull c0, c1;                     // {c_k,c_k+1} natural pairs, warp-uniform
                lds2u64(c0, c1, ca + cq * 16);
                fma2(acc[cq * 2 + 0][0], x0, c0);
                fma2(acc[cq * 2 + 0][1], x1, c0);
                fma2(acc[cq * 2 + 0][2], x2, c0);
                fma2(acc[cq * 2 + 0][3], x3, c0);
                fma2(acc[cq * 2 + 1][0], x0, c1);
                fma2(acc[cq * 2 + 1][1], x1, c1);
                fma2(acc[cq * 2 + 1][2], x2, c1);
                fma2(acc[cq * 2 + 1][3], x3, c1);
            }
        }

        // epilogue: d2 = fl(fl(xn-2s)+cn), running argmin (ascending k, strict <)
        const int kw = p * CPASS + wid * 16;
#pragma unroll
        for (int cp = 0; cp < 8; cp++) {
            int k0 = kw + cp * 2;
            float cn0 = Cn[k0], cn1 = Cn[k0 + 1];
#pragma unroll
            for (int t = 0; t < 4; t++) {
                ull a = acc[cp][t];
                float slo = __uint_as_float((unsigned)(a & 0xffffffffull));
                float shi = __uint_as_float((unsigned)(a >> 32));
                float d2a = __fadd_rn(__fsub_rn(xnr[t], 2.0f * slo), cn0);
                float d2b = __fadd_rn(__fsub_rn(xnr[t], 2.0f * shi), cn1);
                if (d2a < best[t]) { best[t] = d2a; bidx[t] = k0; }
                if (d2b < best[t]) { best[t] = d2b; bidx[t] = k0 + 1; }
            }
        }
    }

    // ---- cross-warp reduce (lexicographic: value, then lowest k) ----
    __syncthreads();   // all passes done; safe to overlay Cs with reduction arrays
#pragma unroll
    for (int t = 0; t < 4; t++) {
        redv[wid * 128 + 4 * l + t] = best[t];
        redi[wid * 128 + 4 * l + t] = bidx[t];
    }
    __syncthreads();

    if (tid < 128) {
        float bv = redv[tid];
        int bi = redi[tid];
#pragma unroll
        for (int w = 1; w < 16; w++) {
            float v = redv[w * 128 + tid];
            int i2 = redi[w * 128 + tid];
            if (v < bv || (v == bv && i2 < bi)) { bv = v; bi = i2; }
        }
        wix[tid] = bi;
        if (outZ) outZ[n0 + tid] = (float)bi;
    }
    __syncthreads();

    // ---- q gather ----
    if (outQ) {
        for (int i = tid; i < 128 * 16; i += NTHREADS) {
            int tt = i >> 4, c4 = i & 15;
            float4 v = *(const float4*)&cb[wix[tt] * DDIM + c4 * 4];
            *(float4*)&outQ[(long)(n0 + tt) * DDIM + c4 * 4] = v;
        }
    }
}

extern "C" void kernel_launch(void* const* d_in, const int* in_sizes, int n_in,
                              void* d_out, int out_size) {
    const float* h = (const float*)d_in[0];
    const float* cb = (const float*)d_in[1];
    float* out = (float*)d_out;

    float* outZ = nullptr;
    float* outQ = nullptr;
    if (out_size >= NTOK + NTOK * DDIM) { outZ = out; outQ = out + NTOK; }
    else if (out_size == NTOK * DDIM)   { outQ = out; }
    else                                { outZ = out; }

    cudaFuncSetAttribute(vq_main, cudaFuncAttributeMaxDynamicSharedMemorySize, SMEM_BYTES);
    vq_prep<<<4, 256>>>(cb);
    vq_main<<<NTOK / TM, NTHREADS, SMEM_BYTES>>>(h, cb, outZ, outQ);
}

// round 15
// speedup vs baseline: 7.9661x; 1.0001x over previous
#include <cuda_runtime.h>
#include <cstdint>

#define DDIM 64
#define KCODES 1024
#define NTOK 131072
#define TM 128
#define NTHREADS 512
#define PASSES 4
#define CPASS 256

typedef unsigned long long ull;

// ---------------- smem layout (bytes) ----------------
#define OFF_XF   0                    // float [64][128] = 32768 (d-major)
#define OFF_CS   32768                // 2 x float [64][256] = 131072 (double-buffered)
#define CS_STRIDE 65536
#define OFF_CN   163840               // float [1024] = 4096
#define OFF_XNS  167936               // float [128]
#define OFF_WIX  168448               // int [128]
#define SMEM_BYTES 168960
// reduction overlays Cs after the last pass:
#define OFF_REDV OFF_CS               // float [16][128] = 8192
#define OFF_REDI (OFF_CS + 8192)      // int   [16][128] = 8192

__device__ float g_cn[KCODES];                        // ||c||^2 (sequential, ref order)
__device__ __align__(16) float g_cbT[DDIM * KCODES];  // transposed codebook [d][k]

__global__ void vq_prep(const float* __restrict__ cb) {
    int k = blockIdx.x * blockDim.x + threadIdx.x;
    if (k >= KCODES) return;
    float acc = 0.f;
#pragma unroll
    for (int d = 0; d < DDIM; d++) {
        float c = cb[k * DDIM + d];
        acc = __fadd_rn(acc, __fmul_rn(c, c));
        g_cbT[d * KCODES + k] = c;
    }
    g_cn[k] = acc;
}

__device__ __forceinline__ uint32_t smem_u32(const void* p) {
    uint32_t a;
    asm("{ .reg .u64 t; cvta.to.shared.u64 t, %1; cvt.u32.u64 %0, t; }" : "=r"(a) : "l"(p));
    return a;
}
__device__ __forceinline__ uint4 lds128(uint32_t a) {
    uint4 v;
    asm volatile("ld.shared.v4.u32 {%0,%1,%2,%3}, [%4];"
                 : "=r"(v.x), "=r"(v.y), "=r"(v.z), "=r"(v.w) : "r"(a));
    return v;
}
__device__ __forceinline__ void lds2u64(ull& a0, ull& a1, uint32_t a) {
    asm volatile("ld.shared.v2.b64 {%0,%1}, [%2];" : "=l"(a0), "=l"(a1) : "r"(a));
}
__device__ __forceinline__ ull rep2(uint32_t x) {
    ull r;
    asm("mov.b64 %0, {%1,%1};" : "=l"(r) : "r"(x));
    return r;
}
__device__ __forceinline__ void fma2(ull& acc, ull x, ull c) {
    asm("fma.rn.f32x2 %0, %1, %2, %0;" : "+l"(acc) : "l"(x), "l"(c));
}

// async-fill one pass's code tile: Cs[buf][d][256] <- g_cbT[d][p*256 + col]
__device__ __forceinline__ void issue_cs(uint32_t sbase, int buf, int p) {
#pragma unroll
    for (int k = 0; k < 8; k++) {
        int i = threadIdx.x + k * NTHREADS;          // uint4 slot 0..4095
        int d = i >> 6;
        int col = (i & 63) << 2;
        uint32_t dst = sbase + OFF_CS + buf * CS_STRIDE + (uint32_t)((d * 256 + col) * 4);
        const char* src = (const char*)(g_cbT + d * KCODES + p * CPASS + col);
        asm volatile("cp.async.ca.shared.global [%0], [%1], 16;"
                     :: "r"(dst), "l"(src) : "memory");
    }
    asm volatile("cp.async.commit_group;" ::: "memory");
}

__global__ __launch_bounds__(NTHREADS, 1)
void vq_main(const float* __restrict__ h, const float* __restrict__ cb,
             float* __restrict__ outZ, float* __restrict__ outQ) {
    extern __shared__ char smem[];
    float* Xf  = (float*)(smem + OFF_XF);    // [64][128]
    float* Cn  = (float*)(smem + OFF_CN);
    float* xns = (float*)(smem + OFF_XNS);
    int*   wix = (int*)(smem + OFF_WIX);
    float* redv = (float*)(smem + OFF_REDV);
    int*   redi = (int*)(smem + OFF_REDI);
    const uint32_t sbase = smem_u32(smem);

    const int tid = threadIdx.x;
    const int wid = tid >> 5;
    const int l = tid & 31;
    const int n0 = blockIdx.x * TM;
    const int b = n0 >> 12;
    const long base = (long)b * 262144 + (n0 & 4095);

    // kick off pass-0 code tile immediately (overlaps the Xf gmem loads below)
    issue_cs(sbase, 0, 0);

    // ---- Xf [d][t]: coalesced LDG.128 -> STS.128, conflict-free ----
    for (int i = tid; i < 64 * 32; i += NTHREADS) {
        int d = i >> 5, t4 = i & 31;
        *(float4*)&Xf[d * 128 + t4 * 4] =
            *(const float4*)(h + base + (long)d * 4096 + t4 * 4);
    }
    for (int i = tid; i < KCODES; i += NTHREADS) Cn[i] = g_cn[i];
    __syncthreads();

    // ---- exact xn (sequential mul-then-add; bit-matches reference, R2-verified) ----
    if (tid < 128) {
        float acc = 0.f;
#pragma unroll
        for (int d = 0; d < 64; d++) {
            float xv = Xf[d * 128 + tid];
            acc = __fadd_rn(acc, __fmul_rn(xv, xv));
        }
        xns[tid] = acc;
    }
    __syncthreads();

    float xnr[4];
    {
        float4 v = *(const float4*)&xns[4 * l];
        xnr[0] = v.x; xnr[1] = v.y; xnr[2] = v.z; xnr[3] = v.w;
    }
    float best[4] = {3.4e38f, 3.4e38f, 3.4e38f, 3.4e38f};
    int bidx[4] = {0, 0, 0, 0};

    const uint32_t xaddr = sbase + OFF_XF + 16u * l;  // this thread's 4 tokens

#pragma unroll 1
    for (int p = 0; p < PASSES; p++) {
        // R13-verified order: wait for buf[p&1], BARRIER (separates pass p-1 reads
        // from the upcoming overwrite), THEN issue prefetch of pass p+1.
        asm volatile("cp.async.wait_group 0;" ::: "memory");
        __syncthreads();
        if (p + 1 < PASSES) issue_cs(sbase, (p + 1) & 1, p + 1);

        const uint32_t caddr = sbase + OFF_CS + (uint32_t)((p & 1) * CS_STRIDE) + 64u * wid;

        // acc[cp][t] = {s(k=2cp), s(k=2cp+1)} for token t (FFMA2 chain from 0 = R2-exact)
        ull acc[8][4];
#pragma unroll
        for (int cp = 0; cp < 8; cp++)
#pragma unroll
            for (int t = 0; t < 4; t++) acc[cp][t] = 0ull;

#pragma unroll 2
        for (int d = 0; d < 64; d++) {
            uint4 xv = lds128(xaddr + (uint32_t)(d * 512));
            ull x0 = rep2(xv.x), x1 = rep2(xv.y), x2 = rep2(xv.z), x3 = rep2(xv.w);
            uint32_t ca = caddr + (uint32_t)(d * 1024);
#pragma unroll
            for (int cq = 0; cq < 4; cq++) {
                ull c0, c1;                     // {c_k,c_k+1} natural pairs, warp-uniform
                lds2u64(c0, c1, ca + cq * 16);
                fma2(acc[cq * 2 + 0][0], x0, c0);
                fma2(acc[cq * 2 + 0][1], x1, c0);
                fma2(acc[cq * 2 + 0][2], x2, c0);
                fma2(acc[cq * 2 + 0][3], x3, c0);
                fma2(acc[cq * 2 + 1][0], x0, c1);
                fma2(acc[cq * 2 + 1][1], x1, c1);
                fma2(acc[cq * 2 + 1][2], x2, c1);
                fma2(acc[cq * 2 + 1][3], x3, c1);
            }
        }

        // epilogue: d2 = fl(fl(xn-2s)+cn), running argmin (ascending k, strict <)
        const int kw = p * CPASS + wid * 16;
#pragma unroll
        for (int cp = 0; cp < 8; cp++) {
            int k0 = kw + cp * 2;
            float cn0 = Cn[k0], cn1 = Cn[k0 + 1];
#pragma unroll
            for (int t = 0; t < 4; t++) {
                ull a = acc[cp][t];
                float slo = __uint_as_float((unsigned)(a & 0xffffffffull));
                float shi = __uint_as_float((unsigned)(a >> 32));
                float d2a = __fadd_rn(__fsub_rn(xnr[t], 2.0f * slo), cn0);
                float d2b = __fadd_rn(__fsub_rn(xnr[t], 2.0f * shi), cn1);
                if (d2a < best[t]) { best[t] = d2a; bidx[t] = k0; }
                if (d2b < best[t]) { best[t] = d2b; bidx[t] = k0 + 1; }
            }
        }
    }

    // ---- cross-warp reduce (lexicographic: value, then lowest k) ----
    __syncthreads();   // all passes done; safe to overlay Cs with reduction arrays
#pragma unroll
    for (int t = 0; t < 4; t++) {
        redv[wid * 128 + 4 * l + t] = best[t];
        redi[wid * 128 + 4 * l + t] = bidx[t];
    }
    __syncthreads();

    if (tid < 128) {
        float bv = redv[tid];
        int bi = redi[tid];
#pragma unroll
        for (int w = 1; w < 16; w++) {
            float v = redv[w * 128 + tid];
            int i2 = redi[w * 128 + tid];
            if (v < bv || (v == bv && i2 < bi)) { bv = v; bi = i2; }
        }
        wix[tid] = bi;
        if (outZ) outZ[n0 + tid] = (float)bi;
    }
    __syncthreads();

    // ---- q gather ----
    if (outQ) {
        for (int i = tid; i < 128 * 16; i += NTHREADS) {
            int tt = i >> 4, c4 = i & 15;
            float4 v = *(const float4*)&cb[wix[tt] * DDIM + c4 * 4];
            *(float4*)&outQ[(long)(n0 + tt) * DDIM + c4 * 4] = v;
        }
    }
}

extern "C" void kernel_launch(void* const* d_in, const int* in_sizes, int n_in,
                              void* d_out, int out_size) {
    const float* h = (const float*)d_in[0];
    const float* cb = (const float*)d_in[1];
    float* out = (float*)d_out;

    float* outZ = nullptr;
    float* outQ = nullptr;
    if (out_size >= NTOK + NTOK * DDIM) { outZ = out; outQ = out + NTOK; }
    else if (out_size == NTOK * DDIM)   { outQ = out; }
    else                                { outZ = out; }

    cudaFuncSetAttribute(vq_main, cudaFuncAttributeMaxDynamicSharedMemorySize, SMEM_BYTES);
    vq_prep<<<4, 256>>>(cb);
    vq_main<<<NTOK / TM, NTHREADS, SMEM_BYTES>>>(h, cb, outZ, outQ);
}